// round 17
// baseline (speedup 1.0000x reference)
#include <cuda_runtime.h>
#include <cuda_bf16.h>
#include <cuda_fp16.h>
#include <math.h>
#include <stdint.h>

#define D_MODEL 1024
#define SEQ     2048
#define NHEADS  16
#define HEADDIM 64
#define MAXB    2

// ---------------------------------------------------------------------------
// Device scratch
// ---------------------------------------------------------------------------
__device__ float g_v[MAXB * SEQ * D_MODEL];
__device__ float g_attn[(size_t)MAXB * NHEADS * SEQ * SEQ];
__device__ uint4 g_afrag[32 * 32 * 512];            // input A fragments
__device__ uint4 g_bfrag[4 * 8 * 32 * 512];         // Wq,Wk,Wv,Wo B-fragments
__device__ uint4 g_ofrag[32 * 32 * 512];            // attention O fragments
__device__ uint4 g_qfrag[MAXB * NHEADS * 16 * 1024];
__device__ uint4 g_kfrag[MAXB * NHEADS * 16 * 1024];
__device__ uint4 g_vfrag[MAXB * NHEADS * 16 * 1024];

// ---------------------------------------------------------------------------
// helpers
// ---------------------------------------------------------------------------
__device__ __forceinline__ uint32_t f2h2(float a, float b) {
    __half2 h = __floats2half2_rn(a, b);
    return *(uint32_t*)&h;
}

__device__ __forceinline__ float ex2(float x) {
    float r;
    asm("ex2.approx.f32 %0, %1;" : "=f"(r) : "f"(x));
    return r;
}

__device__ __forceinline__ void mma_f16(float* c, const uint32_t* a, const uint32_t* b) {
    asm("mma.sync.aligned.m16n8k16.row.col.f32.f16.f16.f32 "
        "{%0,%1,%2,%3}, {%4,%5,%6,%7}, {%8,%9}, {%0,%1,%2,%3};"
        : "+f"(c[0]), "+f"(c[1]), "+f"(c[2]), "+f"(c[3])
        : "r"(a[0]), "r"(a[1]), "r"(a[2]), "r"(a[3]), "r"(b[0]), "r"(b[1]));
}

__device__ __forceinline__ void a_frag_store(
    uint32_t* w, int r8, int c4, const float4& vlo, const float4& vhi)
{
    int cc  = c4 & 15;
    int kq0 = (cc & 7) >> 1;
    int rb  = (cc >= 8) ? 2 : 0;
    int l0 = (r8 * 4 + kq0) * 4;
    int l1 = (r8 * 4 + kq0 + 1) * 4;
    w[l0 + rb]     = f2h2(vlo.x, vlo.y);
    w[l0 + rb + 1] = f2h2(vhi.x, vhi.y);
    w[l1 + rb]     = f2h2(vlo.z, vlo.w);
    w[l1 + rb + 1] = f2h2(vhi.z, vhi.w);
}

// ---------------------------------------------------------------------------
// Prep: fragment buffers for input A and the 4 weight matrices (R15, passing)
// ---------------------------------------------------------------------------
__global__ void __launch_bounds__(256)
prep_frags(const float* __restrict__ A,
           const float* __restrict__ Wq, const float* __restrict__ Wk,
           const float* __restrict__ Wv, const float* __restrict__ Wo,
           uint4* __restrict__ afg, uint4* __restrict__ bfg, int mstrips)
{
    __shared__ uint4 F[8][2][33];
    const int z     = blockIdx.z;
    const int strip = blockIdx.y;
    const int kt    = blockIdx.x;
    const int tid   = threadIdx.x;
    if (z == 0 && strip >= mstrips) return;
    if (z > 0 && strip >= 8) return;

    const int k0 = kt * 32;

    if (z == 0) {
        const int m0 = strip * 128;
        #pragma unroll
        for (int i = 0; i < 2; i++) {
            int idx = tid + i * 256;
            int rp = idx >> 3, c4 = (idx & 7) * 4;
            int mt = rp >> 3, r8 = rp & 7;
            const float* a0 = &A[(size_t)(m0 + mt * 16 + r8) * D_MODEL + k0 + c4];
            float4 vlo = *(const float4*)a0;
            float4 vhi = *(const float4*)(a0 + 8 * D_MODEL);
            a_frag_store((uint32_t*)&F[mt][c4 >> 4][0], r8, c4, vlo, vhi);
        }
    } else {
        const float* W = (z == 1) ? Wq : (z == 2) ? Wk : (z == 3) ? Wv : Wo;
        const int n0 = strip * 128;
        #pragma unroll
        for (int i = 0; i < 2; i++) {
            int idx = tid + i * 256;
            int rp2 = idx >> 5, c42 = (idx & 31) * 4;
            const float* b0 = &W[(size_t)(k0 + 2 * rp2) * D_MODEL + n0 + c42];
            float4 blo = *(const float4*)b0;
            float4 bhi = *(const float4*)(b0 + D_MODEL);
            int kb = rp2 >> 3;
            int tt = rp2 & 7;
            int kq = tt & 3, regsel = tt >> 2;
            float be[4] = {blo.x, blo.y, blo.z, blo.w};
            float bo_[4] = {bhi.x, bhi.y, bhi.z, bhi.w};
            #pragma unroll
            for (int j = 0; j < 4; j++) {
                int n = c42 + j;
                int nt = n >> 3, gg = n & 7;
                uint32_t* w = (uint32_t*)&F[nt >> 1][kb][0];
                w[(gg * 4 + kq) * 4 + (nt & 1) * 2 + regsel] = f2h2(be[j], bo_[j]);
            }
        }
    }
    __syncthreads();

    uint4* dst = (z == 0)
        ? afg + ((size_t)strip * 32 + kt) * 512
        : bfg + (((size_t)(z - 1) * 8 + strip) * 32 + kt) * 512;
    #pragma unroll
    for (int j = tid; j < 512; j += 256)
        dst[j] = F[j >> 6][(j >> 5) & 1][j & 31];
}

// ---------------------------------------------------------------------------
// Fragment GEMM core (R15, passing)
// ---------------------------------------------------------------------------
struct GemmSmem {
    uint4 AF[8][2][33];
    uint4 BF[8][2][33];
};

__device__ __forceinline__ void frag_sts(GemmSmem& s, int tid,
                                         const uint4* sa, const uint4* sb)
{
    #pragma unroll
    for (int i = 0; i < 2; i++) {
        int j = tid + i * 256;
        s.AF[j >> 6][(j >> 5) & 1][j & 31] = sa[i];
        s.BF[j >> 6][(j >> 5) & 1][j & 31] = sb[i];
    }
}

// computes acc for a 128x128 tile from fragment inputs
__device__ __forceinline__ void gemm_frag_mainloop(
    GemmSmem* bufs, const uint4* __restrict__ Ag, const uint4* __restrict__ Bg,
    float acc[2][8][4])
{
    const int tid  = threadIdx.x;
    const int warp = tid >> 5;
    const int lane = tid & 31;
    const int wm   = warp >> 1;
    const int wn   = warp & 1;

    uint4 sa[2], sb[2];
    #pragma unroll
    for (int i = 0; i < 2; i++) {
        sa[i] = Ag[tid + i * 256];
        sb[i] = Bg[tid + i * 256];
    }
    frag_sts(bufs[0], tid, sa, sb);
    __syncthreads();

    const int NT = D_MODEL / 32;
    for (int kt = 0; kt < NT; kt++) {
        GemmSmem& cur = bufs[kt & 1];
        const bool has_next = (kt + 1 < NT);
        if (has_next) {
            #pragma unroll
            for (int i = 0; i < 2; i++) {
                sa[i] = Ag[(kt + 1) * 512 + tid + i * 256];
                sb[i] = Bg[(kt + 1) * 512 + tid + i * 256];
            }
        }

        #pragma unroll
        for (int kb = 0; kb < 2; kb++) {
            uint4 a[2];
            a[0] = cur.AF[wm * 2 + 0][kb][lane];
            a[1] = cur.AF[wm * 2 + 1][kb][lane];
            #pragma unroll
            for (int jn2 = 0; jn2 < 4; jn2++) {
                uint4 b2 = cur.BF[wn * 4 + jn2][kb][lane];
                #pragma unroll
                for (int im = 0; im < 2; im++) {
                    mma_f16(acc[im][2 * jn2 + 0], (const uint32_t*)&a[im], (const uint32_t*)&b2.x);
                    mma_f16(acc[im][2 * jn2 + 1], (const uint32_t*)&a[im], (const uint32_t*)&b2.z);
                }
            }
        }

        if (has_next)
            frag_sts(bufs[(kt + 1) & 1], tid, sa, sb);
        __syncthreads();
    }
}

// QKV projection: z=0 emits Q A-frags, z=1 emits K B-frags, z=2 emits V fp32
__global__ void __launch_bounds__(256, 2)
qkv_frag(const uint4* __restrict__ afg, const uint4* __restrict__ bfg,
         const float* __restrict__ bq, const float* __restrict__ bk,
         const float* __restrict__ bv,
         uint4* __restrict__ qfg, uint4* __restrict__ kfg, float* __restrict__ ov)
{
    extern __shared__ char smem_raw[];
    GemmSmem* bufs = (GemmSmem*)smem_raw;
    const int z = blockIdx.z;
    const float* bias = (z == 0) ? bq : (z == 1) ? bk : bv;
    const uint4* Ag = afg + (size_t)blockIdx.y * 32 * 512;
    const uint4* Bg = bfg + (((size_t)z * 8 + blockIdx.x) * 32) * 512;

    float acc[2][8][4] = {};
    gemm_frag_mainloop(bufs, Ag, Bg, acc);

    const int tid  = threadIdx.x;
    const int warp = tid >> 5;
    const int lane = tid & 31;
    const int g    = lane >> 2;
    const int kq   = lane & 3;
    const int wm   = warp >> 1;
    const int wn   = warp & 1;
    const int m0 = blockIdx.y * 128;
    const int n0 = blockIdx.x * 128;

    if (z == 2) {
        // V: fp32 rows (consumed by prep_v)
        #pragma unroll
        for (int im = 0; im < 2; im++) {
            int mb = m0 + wm * 32 + im * 16;
            #pragma unroll
            for (int jn = 0; jn < 8; jn++) {
                int n = n0 + wn * 64 + jn * 8 + 2 * kq;
                float b0 = bias[n], b1 = bias[n + 1];
                float* p0 = &ov[(size_t)(mb + g) * D_MODEL + n];
                float* p1 = &ov[(size_t)(mb + g + 8) * D_MODEL + n];
                p0[0] = acc[im][jn][0] + b0; p0[1] = acc[im][jn][1] + b1;
                p1[0] = acc[im][jn][2] + b0; p1[1] = acc[im][jn][3] + b1;
            }
        }
        return;
    }

    // Q/K: direct fragment emit
    const int b     = m0 / SEQ;
    const int stile = (m0 % SEQ) >> 7;
    const int head  = blockIdx.x * 2 + wn;
    uint4* dstblk = ((z == 0) ? qfg : kfg)
                  + (((size_t)(b * NHEADS + head) * 16) + stile) * 1024;

    #pragma unroll
    for (int im = 0; im < 2; im++) {
        int mt = wm * 2 + im;   // Q: m16-tile ; K: nt2 (key>>4) — same value
        #pragma unroll
        for (int kb = 0; kb < 4; kb++) {
            int jnE = 2 * kb, jnO = 2 * kb + 1;
            int nE = n0 + wn * 64 + jnE * 8 + 2 * kq;
            int nO = nE + 8;
            float bE0 = bias[nE], bE1 = bias[nE + 1];
            float bO0 = bias[nO], bO1 = bias[nO + 1];
            float e0 = acc[im][jnE][0] + bE0, e1 = acc[im][jnE][1] + bE1;
            float e2 = acc[im][jnE][2] + bE0, e3 = acc[im][jnE][3] + bE1;
            float o0 = acc[im][jnO][0] + bO0, o1 = acc[im][jnO][1] + bO1;
            float o2 = acc[im][jnO][2] + bO0, o3 = acc[im][jnO][3] + bO1;
            uint4 u;
            if (z == 0) {   // Q A-frag: {E rowg, E rowg+8, O rowg, O rowg+8}
                u.x = f2h2(e0, e1); u.y = f2h2(e2, e3);
                u.z = f2h2(o0, o1); u.w = f2h2(o2, o3);
            } else {        // K B-frag: {E rowg, O rowg, E rowg+8, O rowg+8}
                u.x = f2h2(e0, e1); u.y = f2h2(o0, o1);
                u.z = f2h2(e2, e3); u.w = f2h2(o2, o3);
            }
            dstblk[(mt * 4 + kb) * 32 + lane] = u;
        }
    }
}

__global__ void __launch_bounds__(256, 2)
gemm_frag(const uint4* __restrict__ ofg, const uint4* __restrict__ bfg,
          const float* __restrict__ bias, float* __restrict__ C)
{
    extern __shared__ char smem_raw[];
    GemmSmem* bufs = (GemmSmem*)smem_raw;
    const uint4* Ag = ofg + (size_t)blockIdx.y * 32 * 512;
    const uint4* Bg = bfg + (((size_t)3 * 8 + blockIdx.x) * 32) * 512;

    float acc[2][8][4] = {};
    gemm_frag_mainloop(bufs, Ag, Bg, acc);

    const int tid  = threadIdx.x;
    const int warp = tid >> 5;
    const int lane = tid & 31;
    const int g    = lane >> 2;
    const int kq   = lane & 3;
    const int wm   = warp >> 1;
    const int wn   = warp & 1;
    const int m0 = blockIdx.y * 128;
    const int n0 = blockIdx.x * 128;

    #pragma unroll
    for (int im = 0; im < 2; im++) {
        int mb = m0 + wm * 32 + im * 16;
        #pragma unroll
        for (int jn = 0; jn < 8; jn++) {
            int n = n0 + wn * 64 + jn * 8 + 2 * kq;
            float b0 = bias[n], b1 = bias[n + 1];
            float* p0 = &C[(size_t)(mb + g) * D_MODEL + n];
            float* p1 = &C[(size_t)(mb + g + 8) * D_MODEL + n];
            p0[0] = acc[im][jn][0] + b0; p0[1] = acc[im][jn][1] + b1;
            p1[0] = acc[im][jn][2] + b0; p1[1] = acc[im][jn][3] + b1;
        }
    }
}

// ---------------------------------------------------------------------------
// Prep: V fragments per (bh, 128-tile). B-frag [4nt2(d)][8kb(key)][32].
// ---------------------------------------------------------------------------
__global__ void __launch_bounds__(256)
prep_v(const float* __restrict__ vb, uint4* __restrict__ vfg)
{
    __shared__ uint4 VF[4][8][33];
    const int bh   = blockIdx.y;
    const int tile = blockIdx.x;
    const int tid  = threadIdx.x;
    const int b = bh >> 4;
    const int h = bh & 15;

    const float* base = vb + (size_t)b * SEQ * D_MODEL + h * HEADDIM;
    const int n0 = tile * 128;
    #pragma unroll
    for (int i = 0; i < 4; i++) {
        int idx = tid + i * 256;
        int rp = idx >> 4;
        int c4 = (idx & 15) * 4;
        const float* p = &base[(size_t)(n0 + 2 * rp) * D_MODEL + c4];
        float4 ve = *(const float4*)p;
        float4 vo = *(const float4*)(p + D_MODEL);
        int kb = rp >> 3;
        int tt = rp & 7;
        int kqv = tt & 3, regsel = tt >> 2;
        float e[4] = {ve.x, ve.y, ve.z, ve.w};
        float o[4] = {vo.x, vo.y, vo.z, vo.w};
        #pragma unroll
        for (int j = 0; j < 4; j++) {
            int d = c4 + j;
            int nt = d >> 3, gg = d & 7;
            uint32_t* w = (uint32_t*)&VF[nt >> 1][kb][0];
            w[(gg * 4 + kqv) * 4 + (nt & 1) * 2 + regsel] = f2h2(e[j], o[j]);
        }
    }
    __syncthreads();

    uint4* dst = vfg + ((size_t)bh * 16 + tile) * 1024;
    #pragma unroll
    for (int j = tid; j < 1024; j += 256)
        dst[j] = VF[j >> 8][(j >> 5) & 7][j & 31];
}

// ---------------------------------------------------------------------------
// Fused attention on prebuilt fragments (sweep-2 now register-staged)
// ---------------------------------------------------------------------------
struct FusedSmem {
    uint4 QF[8][4][33];
    uint4 KFa[8][4][33];
    uint4 KFb[8][4][33];
    uint4 VF[4][8][33];
    uint4 PF[8][8][33];
    float red[2][128];
    float sinvl[128];
};

__global__ void __launch_bounds__(256, 2)
attn_fused(const uint4* __restrict__ qfg, const uint4* __restrict__ kfg,
           const uint4* __restrict__ vfg, const float* __restrict__ scale_ptr,
           float* __restrict__ attn, uint4* __restrict__ ofg)
{
    extern __shared__ char smem_raw[];
    FusedSmem& sm = *(FusedSmem*)smem_raw;

    const int tid  = threadIdx.x;
    const int warp = tid >> 5;
    const int lane = tid & 31;
    const int g    = lane >> 2;
    const int kq   = lane & 3;
    const int wm   = warp >> 1;
    const int wn   = warp & 1;

    const int bh = blockIdx.y;
    const int b  = bh >> 4;
    const int h  = bh & 15;
    const int m0 = blockIdx.x * 128;

    const float sc = scale_ptr[0] * 1.44269504088896f;

    const uint4* Qg = qfg + ((size_t)bh * 16 + blockIdx.x) * 1024;
    const uint4* Kg = kfg + (size_t)bh * 16 * 1024;
    const uint4* Vg = vfg + (size_t)bh * 16 * 1024;
    float* pstrip = attn + ((size_t)bh * SEQ + m0) * SEQ;

    // ---- Q frags (once) ----
    #pragma unroll
    for (int i = 0; i < 4; i++) {
        int j = tid + i * 256;
        sm.QF[j >> 7][(j >> 5) & 3][j & 31] = Qg[j];
    }

    const int NIT = SEQ / 128;

    // ================= Sweep 1: row sums =================
    {
        float l_acc[2][2] = {};
        uint4 kreg[4];

        #pragma unroll
        for (int i = 0; i < 4; i++) kreg[i] = Kg[tid + i * 256];
        #pragma unroll
        for (int i = 0; i < 4; i++) {
            int j = tid + i * 256;
            sm.KFa[j >> 7][(j >> 5) & 3][j & 31] = kreg[i];
        }
        __syncthreads();

        for (int iter = 0; iter < NIT; iter++) {
            const bool has_next = (iter + 1 < NIT);
            if (has_next)
                #pragma unroll
                for (int i = 0; i < 4; i++)
                    kreg[i] = Kg[(iter + 1) * 1024 + tid + i * 256];

            uint4 (*KFc)[4][33] = (iter & 1) ? sm.KFb : sm.KFa;
            float acc[2][8][4] = {};
            #pragma unroll
            for (int kb = 0; kb < 4; kb++) {
                uint4 a[2];
                a[0] = sm.QF[wm * 2 + 0][kb][lane];
                a[1] = sm.QF[wm * 2 + 1][kb][lane];
                #pragma unroll
                for (int jn2 = 0; jn2 < 4; jn2++) {
                    uint4 kf = KFc[wn * 4 + jn2][kb][lane];
                    #pragma unroll
                    for (int im = 0; im < 2; im++) {
                        mma_f16(acc[im][2 * jn2 + 0], (const uint32_t*)&a[im], (const uint32_t*)&kf.x);
                        mma_f16(acc[im][2 * jn2 + 1], (const uint32_t*)&a[im], (const uint32_t*)&kf.z);
                    }
                }
            }
            #pragma unroll
            for (int im = 0; im < 2; im++)
                #pragma unroll
                for (int jn = 0; jn < 8; jn++) {
                    l_acc[im][0] += ex2(acc[im][jn][0] * sc) + ex2(acc[im][jn][1] * sc);
                    l_acc[im][1] += ex2(acc[im][jn][2] * sc) + ex2(acc[im][jn][3] * sc);
                }

            if (has_next) {
                uint4 (*KFn)[4][33] = (iter & 1) ? sm.KFa : sm.KFb;
                #pragma unroll
                for (int i = 0; i < 4; i++) {
                    int j = tid + i * 256;
                    KFn[j >> 7][(j >> 5) & 3][j & 31] = kreg[i];
                }
            }
            __syncthreads();
        }

        #pragma unroll
        for (int im = 0; im < 2; im++)
            #pragma unroll
            for (int rh = 0; rh < 2; rh++) {
                l_acc[im][rh] += __shfl_xor_sync(0xffffffff, l_acc[im][rh], 1);
                l_acc[im][rh] += __shfl_xor_sync(0xffffffff, l_acc[im][rh], 2);
            }
        if (kq == 0) {
            #pragma unroll
            for (int im = 0; im < 2; im++)
                #pragma unroll
                for (int rh = 0; rh < 2; rh++)
                    sm.red[wn][wm * 32 + im * 16 + rh * 8 + g] = l_acc[im][rh];
        }
        __syncthreads();
        if (tid < 128)
            sm.sinvl[tid] = 1.0f / (sm.red[0][tid] + sm.red[1][tid]);
        __syncthreads();
    }

    // ================= Sweep 2: write normalized P, accumulate O =================
    float acc_o[2][4][4] = {};
    float il[2][2];
    #pragma unroll
    for (int im = 0; im < 2; im++) {
        il[im][0] = sm.sinvl[wm * 32 + im * 16 + g];
        il[im][1] = sm.sinvl[wm * 32 + im * 16 + g + 8];
    }

    // prologue: stage tile 0
    {
        #pragma unroll
        for (int i = 0; i < 4; i++) {
            int j = tid + i * 256;
            sm.KFa[j >> 7][(j >> 5) & 3][j & 31] = Kg[j];
            sm.VF[j >> 8][(j >> 5) & 7][j & 31] = Vg[j];
        }
        __syncthreads();
    }

    for (int iter = 0; iter < NIT; iter++) {
        const int n0 = iter * 128;
        const bool has_next = (iter + 1 < NIT);

        // --- S MMA (reads KFa) ---
        float acc[2][8][4] = {};
        #pragma unroll
        for (int kb = 0; kb < 4; kb++) {
            uint4 a[2];
            a[0] = sm.QF[wm * 2 + 0][kb][lane];
            a[1] = sm.QF[wm * 2 + 1][kb][lane];
            #pragma unroll
            for (int jn2 = 0; jn2 < 4; jn2++) {
                uint4 kf = sm.KFa[wn * 4 + jn2][kb][lane];
                #pragma unroll
                for (int im = 0; im < 2; im++) {
                    mma_f16(acc[im][2 * jn2 + 0], (const uint32_t*)&a[im], (const uint32_t*)&kf.x);
                    mma_f16(acc[im][2 * jn2 + 1], (const uint32_t*)&a[im], (const uint32_t*)&kf.z);
                }
            }
        }

        // --- exp * invl, write P once, scatter p-frags to PF ---
        #pragma unroll
        for (int im = 0; im < 2; im++) {
            int mt = wm * 2 + im;
            int mb = wm * 32 + im * 16;
            #pragma unroll
            for (int jn = 0; jn < 8; jn++) {
                int c = wn * 64 + jn * 8 + 2 * kq;
                float p0 = ex2(acc[im][jn][0] * sc) * il[im][0];
                float p1 = ex2(acc[im][jn][1] * sc) * il[im][0];
                float p2 = ex2(acc[im][jn][2] * sc) * il[im][1];
                float p3 = ex2(acc[im][jn][3] * sc) * il[im][1];
                *(float2*)&pstrip[(size_t)(mb + g) * SEQ + n0 + c]     = make_float2(p0, p1);
                *(float2*)&pstrip[(size_t)(mb + g + 8) * SEQ + n0 + c] = make_float2(p2, p3);
                int kbp = wn * 4 + (jn >> 1);
                uint32_t* pfb = (uint32_t*)&sm.PF[mt][kbp][0];
                int base = (g * 4 + kq) * 4 + (jn & 1) * 2;
                *(uint2*)&pfb[base] = make_uint2(f2h2(p0, p1), f2h2(p2, p3));
            }
        }
        __syncthreads();   // PF ready; KFa reads done

        // --- prefetch next K/V tiles into registers (overlaps PV) ---
        uint4 kreg[4], vreg[4];
        if (has_next) {
            #pragma unroll
            for (int i = 0; i < 4; i++) {
                kreg[i] = Kg[(iter + 1) * 1024 + tid + i * 256];
                vreg[i] = Vg[(iter + 1) * 1024 + tid + i * 256];
            }
        }

        // --- PV MMA ---
        #pragma unroll
        for (int kb = 0; kb < 8; kb++) {
            uint4 a[2];
            a[0] = sm.PF[wm * 2 + 0][kb][lane];
            a[1] = sm.PF[wm * 2 + 1][kb][lane];
            #pragma unroll
            for (int jn2 = 0; jn2 < 2; jn2++) {
                uint4 vf = sm.VF[wn * 2 + jn2][kb][lane];
                #pragma unroll
                for (int im = 0; im < 2; im++) {
                    mma_f16(acc_o[im][2 * jn2 + 0], (const uint32_t*)&a[im], (const uint32_t*)&vf.x);
                    mma_f16(acc_o[im][2 * jn2 + 1], (const uint32_t*)&a[im], (const uint32_t*)&vf.z);
                }
            }
        }
        __syncthreads();   // VF/PF reads done

        if (has_next) {
            #pragma unroll
            for (int i = 0; i < 4; i++) {
                int j = tid + i * 256;
                sm.KFa[j >> 7][(j >> 5) & 3][j & 31] = kreg[i];
                sm.VF[j >> 8][(j >> 5) & 7][j & 31] = vreg[i];
            }
            __syncthreads();
        }
    }

    // ---- write O directly as fp16 A-fragments for the output projection ----
    {
        const int strip = (b * SEQ + m0) >> 7;
        const int kt32  = h * 2 + wn;
        uint4* obase = ofg + ((size_t)strip * 32 + kt32) * 512;
        #pragma unroll
        for (int im = 0; im < 2; im++) {
            int mt = wm * 2 + im;
            #pragma unroll
            for (int kb = 0; kb < 2; kb++) {
                float* a0 = acc_o[im][2 * kb + 0];
                float* a1 = acc_o[im][2 * kb + 1];
                uint4 u;
                u.x = f2h2(a0[0], a0[1]);
                u.y = f2h2(a0[2], a0[3]);
                u.z = f2h2(a1[0], a1[1]);
                u.w = f2h2(a1[2], a1[3]);
                obase[(mt * 2 + kb) * 32 + lane] = u;
            }
        }
    }
}

// ---------------------------------------------------------------------------
// Launch
// ---------------------------------------------------------------------------
extern "C" void kernel_launch(void* const* d_in, const int* in_sizes, int n_in,
                              void* d_out, int out_size)
{
    const float* Q     = (const float*)d_in[0];
    const float* Wq    = (const float*)d_in[1];
    const float* bq    = (const float*)d_in[2];
    const float* Wk    = (const float*)d_in[3];
    const float* bk    = (const float*)d_in[4];
    const float* Wv    = (const float*)d_in[5];
    const float* bv    = (const float*)d_in[6];
    const float* Wo    = (const float*)d_in[7];
    const float* bo    = (const float*)d_in[8];
    const float* scale = (const float*)d_in[9];

    const int M = in_sizes[0] / D_MODEL;
    const int B = M / SEQ;
    const int mstrips = M / 128;

    float* out = (float*)d_out;

    float *vp, *ap;
    uint4 *afp, *bfp, *ofp, *qfp, *kfp, *vfp;
    cudaGetSymbolAddress((void**)&vp, g_v);
    cudaGetSymbolAddress((void**)&ap, g_attn);
    cudaGetSymbolAddress((void**)&afp, g_afrag);
    cudaGetSymbolAddress((void**)&bfp, g_bfrag);
    cudaGetSymbolAddress((void**)&ofp, g_ofrag);
    cudaGetSymbolAddress((void**)&qfp, g_qfrag);
    cudaGetSymbolAddress((void**)&kfp, g_kfrag);
    cudaGetSymbolAddress((void**)&vfp, g_vfrag);

    const size_t out_elems = (size_t)M * D_MODEL;
    float* attn = ((size_t)out_size > out_elems) ? (out + out_elems) : ap;

    const int gemm_smem  = (int)(2 * sizeof(GemmSmem));
    const int fused_smem = (int)sizeof(FusedSmem);
    cudaFuncSetAttribute(qkv_frag, cudaFuncAttributeMaxDynamicSharedMemorySize, gemm_smem);
    cudaFuncSetAttribute(gemm_frag, cudaFuncAttributeMaxDynamicSharedMemorySize, gemm_smem);
    cudaFuncSetAttribute(attn_fused, cudaFuncAttributeMaxDynamicSharedMemorySize, fused_smem);

    // 1) fragment prep (A + 4 weights)
    dim3 gprep(32, mstrips > 8 ? mstrips : 8, 5);
    prep_frags<<<gprep, 256>>>(Q, Wq, Wk, Wv, Wo, afp, bfp, mstrips);

    // 2) QKV projections: Q,K emit fragments directly; V emits fp32
    dim3 gqkv(D_MODEL / 128, mstrips, 3);
    qkv_frag<<<gqkv, 256, gemm_smem>>>(afp, bfp, bq, bk, bv, qfp, kfp, vp);

    // 3) V fragment prep
    dim3 gpv(SEQ / 128, B * NHEADS);
    prep_v<<<gpv, 256>>>(vp, vfp);

    // 4) fused attention on fragments
    dim3 gfa(SEQ / 128, B * NHEADS);
    attn_fused<<<gfa, 256, fused_smem>>>(qfp, kfp, vfp, scale, attn, ofp);

    // 5) output projection from O fragments
    dim3 gproj(D_MODEL / 128, mstrips);
    gemm_frag<<<gproj, 256, gemm_smem>>>(ofp, bfp, bo, out);
}